// round 1
// baseline (speedup 1.0000x reference)
#include <cuda_runtime.h>

#define N_NODES 50000
#define D 128
#define N_EDGES_MAX 800000

// Scratch for aggregated features h = segment_sum(x[src], dst).
// Device global (no allocations allowed in kernel_launch).
__device__ float g_h[(size_t)N_NODES * D];

// ---------------------------------------------------------------------------
// Kernel 1: zero the scratch accumulator
// ---------------------------------------------------------------------------
__global__ void zero_h_kernel() {
    int i = blockIdx.x * blockDim.x + threadIdx.x;
    const int n4 = N_NODES * D / 4;
    if (i < n4) {
        reinterpret_cast<float4*>(g_h)[i] = make_float4(0.f, 0.f, 0.f, 0.f);
    }
}

// ---------------------------------------------------------------------------
// Kernel 2: edge scatter — one warp per edge.
// Each lane moves a float4 (32 lanes x 16B = 512B = one full 128-float row).
// Uses red.global.add.v4.f32 (no-return vector atomic) into g_h[dst].
// x fits in L2 (25.6MB), so gathers are L2 hits after warmup.
// ---------------------------------------------------------------------------
__global__ void scatter_edges_kernel(const float* __restrict__ x,
                                     const int* __restrict__ src,
                                     const int* __restrict__ dst,
                                     int n_edges) {
    int gw = (blockIdx.x * blockDim.x + threadIdx.x) >> 5;  // global warp id = edge id
    int lane = threadIdx.x & 31;
    if (gw >= n_edges) return;

    int s = __ldg(src + gw);
    int d = __ldg(dst + gw);

    const float4* xrow = reinterpret_cast<const float4*>(x + (size_t)s * D);
    float4 v = __ldg(xrow + lane);

    float* hp = g_h + (size_t)d * D + lane * 4;
    asm volatile("red.global.add.v4.f32 [%0], {%1, %2, %3, %4};"
                 :: "l"(hp), "f"(v.x), "f"(v.y), "f"(v.z), "f"(v.w)
                 : "memory");
}

// ---------------------------------------------------------------------------
// Kernel 3: out = h @ W^T + b
// h: [N_NODES, 128], W: [128, 128] (out_feats x in_feats), b: [128]
// Tiled SGEMM: BM=128, BN=128 (full width), BK=16, 256 threads, 8x8 per thread.
// Both smem tiles stored K-major so inner loads are along the fast dimension.
// ---------------------------------------------------------------------------
__global__ __launch_bounds__(256) void gemm_bias_kernel(
    const float* __restrict__ W,
    const float* __restrict__ b,
    float* __restrict__ out) {

    __shared__ float As[16][128];  // As[k][row]  (h tile, transposed)
    __shared__ float Bs[16][128];  // Bs[k][ocol] (W tile, transposed: Bs[k][o] = W[o][k])

    const int tid = threadIdx.x;
    const int tx = tid & 15;       // 0..15 -> output-column group
    const int ty = tid >> 4;       // 0..15 -> output-row group
    const int row0 = blockIdx.x * 128;

    float acc[8][8];
#pragma unroll
    for (int i = 0; i < 8; i++)
#pragma unroll
        for (int j = 0; j < 8; j++) acc[i][j] = 0.f;

    for (int k0 = 0; k0 < 128; k0 += 16) {
        // --- load A tile (h): 128 rows x 16 k, 512 float4, 2 per thread ---
#pragma unroll
        for (int t = 0; t < 2; t++) {
            int fid = tid * 2 + t;       // 0..511
            int r = fid >> 2;            // 0..127
            int kc = (fid & 3) * 4;      // 0,4,8,12
            int row = row0 + r;
            float4 v = make_float4(0.f, 0.f, 0.f, 0.f);
            if (row < N_NODES)
                v = *reinterpret_cast<const float4*>(g_h + (size_t)row * D + k0 + kc);
            As[kc + 0][r] = v.x;
            As[kc + 1][r] = v.y;
            As[kc + 2][r] = v.z;
            As[kc + 3][r] = v.w;
        }
        // --- load B tile (W): Bs[k][o] = W[o][k0+k] ---
#pragma unroll
        for (int t = 0; t < 2; t++) {
            int fid = tid * 2 + t;
            int o = fid >> 2;            // 0..127
            int kc = (fid & 3) * 4;
            float4 v = *reinterpret_cast<const float4*>(W + (size_t)o * D + k0 + kc);
            Bs[kc + 0][o] = v.x;
            Bs[kc + 1][o] = v.y;
            Bs[kc + 2][o] = v.z;
            Bs[kc + 3][o] = v.w;
        }
        __syncthreads();

#pragma unroll
        for (int kk = 0; kk < 16; kk++) {
            float ra[8], rb[8];
#pragma unroll
            for (int i = 0; i < 8; i++) ra[i] = As[kk][ty * 8 + i];
#pragma unroll
            for (int j = 0; j < 8; j++) rb[j] = Bs[kk][tx * 8 + j];
#pragma unroll
            for (int i = 0; i < 8; i++)
#pragma unroll
                for (int j = 0; j < 8; j++)
                    acc[i][j] += ra[i] * rb[j];
        }
        __syncthreads();
    }

    // --- epilogue: add bias, store ---
#pragma unroll
    for (int i = 0; i < 8; i++) {
        int row = row0 + ty * 8 + i;
        if (row >= N_NODES) continue;
#pragma unroll
        for (int j = 0; j < 8; j += 4) {
            int col = tx * 8 + j;
            float4 v;
            v.x = acc[i][j + 0] + __ldg(b + col + 0);
            v.y = acc[i][j + 1] + __ldg(b + col + 1);
            v.z = acc[i][j + 2] + __ldg(b + col + 2);
            v.w = acc[i][j + 3] + __ldg(b + col + 3);
            *reinterpret_cast<float4*>(out + (size_t)row * D + col) = v;
        }
    }
}

// ---------------------------------------------------------------------------
// Launch: inputs in metadata order: x, src, dst, W, b
// ---------------------------------------------------------------------------
extern "C" void kernel_launch(void* const* d_in, const int* in_sizes, int n_in,
                              void* d_out, int out_size) {
    const float* x   = (const float*)d_in[0];
    const int*   src = (const int*)d_in[1];
    const int*   dst = (const int*)d_in[2];
    const float* W   = (const float*)d_in[3];
    const float* b   = (const float*)d_in[4];
    float* out = (float*)d_out;

    const int n_edges = in_sizes[1];

    // 1) zero accumulator
    {
        int n4 = N_NODES * D / 4;
        int blocks = (n4 + 255) / 256;
        zero_h_kernel<<<blocks, 256>>>();
    }
    // 2) scatter-add edges (one warp per edge)
    {
        long long total_threads = (long long)n_edges * 32;
        int blocks = (int)((total_threads + 255) / 256);
        scatter_edges_kernel<<<blocks, 256>>>(x, src, dst, n_edges);
    }
    // 3) GEMM + bias
    {
        int blocks = (N_NODES + 127) / 128;
        gemm_bias_kernel<<<blocks, 256>>>(W, b, out);
    }
}